// round 3
// baseline (speedup 1.0000x reference)
#include <cuda_runtime.h>
#include <math.h>

#define LN_EPS 1e-5f
#define MAXN 50048
#define MAXE 600064
#define NGRAPH 64

// ---------------- scratch (device globals; 16B-aligned via float4) ----------
__device__ int    g_mode64;            // 1 if index inputs are int64, 0 if int32
__device__ int    g_deg[MAXN];
__device__ int    g_off[MAXN];
__device__ int    g_cursor[MAXN];
__device__ int    g_csr[MAXE];
__device__ float4 g_agg[(size_t)MAXN * 32];   // 128 floats per node
__device__ float4 g_h1 [(size_t)MAXN * 32];
__device__ float4 g_h2 [(size_t)MAXN * 32];
__device__ float  g_gsum[NGRAPH * 64];
__device__ float  g_gmax[NGRAPH * 64];
__device__ int    g_gcnt[NGRAPH];
__device__ float  g_z2[NGRAPH * 128];

// ---------------- index-dtype probe ------------------------------------------
// If the buffer is really int32 but we read int64, adjacent random values in
// [0, N) combine to huge numbers -> out of [0, N) -> detected.
__global__ void k_probe(const void* ei, int E, int Nn) {
    const long long* e64 = (const long long*)ei;
    bool ok64 = true;
    for (int i = 0; i < 8; i++) {
        long long s = e64[i];
        long long d = e64[(size_t)E + i];
        if (s < 0 || s >= Nn || d < 0 || d >= Nn) ok64 = false;
    }
    g_mode64 = ok64 ? 1 : 0;
}

__device__ __forceinline__ int load_idx(const void* p, size_t i) {
    if (g_mode64) return (int)((const long long*)p)[i];
    return ((const int*)p)[i];
}

// ---------------- init ------------------------------------------------------
__global__ void k_init(int Nn) {
    int i = blockIdx.x * blockDim.x + threadIdx.x;
    if (i < Nn) g_deg[i] = 0;
    if (i < NGRAPH * 64) { g_gsum[i] = 0.f; g_gmax[i] = 0.f; }
    if (i < NGRAPH) g_gcnt[i] = 0;
}

// ---------------- CSR build --------------------------------------------------
__global__ void k_hist(const void* __restrict__ ei, int E, int Nn) {
    int e = blockIdx.x * blockDim.x + threadIdx.x;
    if (e >= E) return;
    int dst = load_idx(ei, (size_t)E + e);
    if (dst >= 0 && dst < Nn) atomicAdd(&g_deg[dst], 1);
}

__global__ void k_scan(int Nn) {
    __shared__ int sums[1024];
    int t = threadIdx.x;
    int chunk = (Nn + 1023) / 1024;
    int b = t * chunk;
    int s = 0;
    for (int j = 0; j < chunk; j++) {
        int i = b + j;
        if (i < Nn) s += g_deg[i];
    }
    sums[t] = s;
    __syncthreads();
    for (int d = 1; d < 1024; d <<= 1) {
        int v = (t >= d) ? sums[t - d] : 0;
        __syncthreads();
        sums[t] += v;
        __syncthreads();
    }
    int run = (t == 0) ? 0 : sums[t - 1];
    for (int j = 0; j < chunk; j++) {
        int i = b + j;
        if (i < Nn) {
            g_off[i] = run;
            g_cursor[i] = run;
            run += g_deg[i];
        }
    }
}

__global__ void k_fill(const void* __restrict__ ei, int E, int Nn) {
    int e = blockIdx.x * blockDim.x + threadIdx.x;
    if (e >= E) return;
    int src = load_idx(ei, (size_t)e);
    int dst = load_idx(ei, (size_t)E + e);
    if (src < 0 || src >= Nn || dst < 0 || dst >= Nn) return;
    int p = atomicAdd(&g_cursor[dst], 1);
    if (p >= 0 && p < MAXE) g_csr[p] = src;
}

// ---------------- mean aggregation: one warp per node -----------------------
__global__ void k_agg(const float4* __restrict__ xin, float4* __restrict__ agg, int Nn) {
    int w = (blockIdx.x * blockDim.x + threadIdx.x) >> 5;
    int lane = threadIdx.x & 31;
    if (w >= Nn) return;
    int s = g_off[w];
    int d = g_deg[w];
    float4 acc = make_float4(0.f, 0.f, 0.f, 0.f);
    int e = 0;
    for (; e + 1 < d; e += 2) {
        int j0 = g_csr[s + e];
        int j1 = g_csr[s + e + 1];
        float4 v0 = __ldg(xin + (size_t)j0 * 32 + lane);
        float4 v1 = __ldg(xin + (size_t)j1 * 32 + lane);
        acc.x += v0.x; acc.y += v0.y; acc.z += v0.z; acc.w += v0.w;
        acc.x += v1.x; acc.y += v1.y; acc.z += v1.z; acc.w += v1.w;
    }
    if (e < d) {
        int j = g_csr[s + e];
        float4 v = __ldg(xin + (size_t)j * 32 + lane);
        acc.x += v.x; acc.y += v.y; acc.z += v.z; acc.w += v.w;
    }
    float inv = (d > 0) ? (1.f / (float)d) : 0.f;
    acc.x *= inv; acc.y *= inv; acc.z *= inv; acc.w *= inv;
    agg[(size_t)w * 32 + lane] = acc;
}

// ---------------- fused GEMM + bias + LayerNorm + ReLU ----------------------
template <int TN>
__global__ void __launch_bounds__(256) k_gemm_ln(
    const float* __restrict__ agg, const float* __restrict__ xin,
    const float* __restrict__ Wl, const float* __restrict__ Wr,
    const float* __restrict__ bl, const float* __restrict__ gm,
    const float* __restrict__ bt, float* __restrict__ out, int Nn)
{
    constexpr int BM = 128;
    constexpr int BK = 16;
    constexpr int W  = TN / 16;
    constexpr int APAD = BM + 4;
    constexpr int BPAD = TN + 4;

    __shared__ float As[BK][APAD];
    __shared__ float Bs[BK][BPAD];
    __shared__ float2 red[BM * 16];

    int tid = threadIdx.x;
    int tx = tid & 15;
    int ty = tid >> 4;
    int m0 = blockIdx.x * BM;

    float acc[8][W];
#pragma unroll
    for (int i = 0; i < 8; i++)
#pragma unroll
        for (int j = 0; j < W; j++) acc[i][j] = 0.f;

    for (int k0 = 0; k0 < 256; k0 += BK) {
        const float* Asrc = (k0 < 128) ? agg : xin;
        const float* Wsrc = (k0 < 128) ? Wl : Wr;
        int kbase = k0 & 127;
#pragma unroll
        for (int j = 0; j < 8; j++) {
            int idx = tid + j * 256;
            int m = idx >> 4, kk = idx & 15;
            int node = m0 + m;
            float v = (node < Nn) ? Asrc[(size_t)node * 128 + kbase + kk] : 0.f;
            As[kk][m] = v;
        }
#pragma unroll
        for (int j = 0; j < (BK * TN) / 256; j++) {
            int idx = tid + j * 256;
            int o = idx >> 4, kk = idx & 15;
            Bs[kk][o] = Wsrc[o * 128 + kbase + kk];
        }
        __syncthreads();
#pragma unroll
        for (int kk = 0; kk < BK; kk++) {
            float a[8], b[W];
#pragma unroll
            for (int i = 0; i < 8; i++) a[i] = As[kk][ty * 8 + i];
#pragma unroll
            for (int j = 0; j < W; j++) b[j] = Bs[kk][tx * W + j];
#pragma unroll
            for (int i = 0; i < 8; i++)
#pragma unroll
                for (int j = 0; j < W; j++) acc[i][j] += a[i] * b[j];
        }
        __syncthreads();
    }

    float blv[W], gv[W], bv[W];
#pragma unroll
    for (int j = 0; j < W; j++) {
        int o = tx * W + j;
        blv[j] = bl[o];
        gv[j]  = gm[o];
        bv[j]  = bt[o];
    }
#pragma unroll
    for (int i = 0; i < 8; i++)
#pragma unroll
        for (int j = 0; j < W; j++) acc[i][j] += blv[j];

#pragma unroll
    for (int i = 0; i < 8; i++) {
        float s = 0.f, s2 = 0.f;
#pragma unroll
        for (int j = 0; j < W; j++) {
            s += acc[i][j];
            s2 += acc[i][j] * acc[i][j];
        }
        red[(ty * 8 + i) * 16 + tx] = make_float2(s, s2);
    }
    __syncthreads();

#pragma unroll
    for (int i = 0; i < 8; i++) {
        int row = ty * 8 + i;
        float s = 0.f, s2 = 0.f;
#pragma unroll
        for (int t = 0; t < 16; t++) {
            float2 v = red[row * 16 + t];
            s += v.x;
            s2 += v.y;
        }
        float mu = s * (1.f / (float)TN);
        float var = s2 * (1.f / (float)TN) - mu * mu;
        float rinv = rsqrtf(var + LN_EPS);
        int node = m0 + row;
        if (node < Nn) {
#pragma unroll
            for (int j = 0; j < W; j++) {
                float val = (acc[i][j] - mu) * rinv * gv[j] + bv[j];
                out[(size_t)node * TN + tx * W + j] = fmaxf(val, 0.f);
            }
        }
    }
}

// ---------------- graph pooling: mean + max over sorted batch ---------------
__global__ void k_pool(const float* __restrict__ h, const void* __restrict__ batch, int Nn) {
    const int NPW = 64;
    int w = (blockIdx.x * blockDim.x + threadIdx.x) >> 5;
    int lane = threadIdx.x & 31;
    int start = w * NPW;
    if (start >= Nn) return;
    int end = min(start + NPW, Nn);

    float s0 = 0.f, s1 = 0.f, mx0 = 0.f, mx1 = 0.f;
    int cur = load_idx(batch, (size_t)start);
    if (cur < 0) cur = 0;
    if (cur >= NGRAPH) cur = NGRAPH - 1;
    int cnt = 0;
    for (int i = start; i < end; i++) {
        int g = load_idx(batch, (size_t)i);
        if (g < 0) g = 0;
        if (g >= NGRAPH) g = NGRAPH - 1;
        if (g != cur) {
            atomicAdd(&g_gsum[cur * 64 + lane], s0);
            atomicAdd(&g_gsum[cur * 64 + lane + 32], s1);
            atomicMax((int*)&g_gmax[cur * 64 + lane], __float_as_int(mx0));
            atomicMax((int*)&g_gmax[cur * 64 + lane + 32], __float_as_int(mx1));
            if (lane == 0) atomicAdd(&g_gcnt[cur], cnt);
            s0 = s1 = mx0 = mx1 = 0.f;
            cnt = 0;
            cur = g;
        }
        float v0 = h[(size_t)i * 64 + lane];
        float v1 = h[(size_t)i * 64 + lane + 32];
        s0 += v0; s1 += v1;
        mx0 = fmaxf(mx0, v0);
        mx1 = fmaxf(mx1, v1);
        cnt++;
    }
    atomicAdd(&g_gsum[cur * 64 + lane], s0);
    atomicAdd(&g_gsum[cur * 64 + lane + 32], s1);
    atomicMax((int*)&g_gmax[cur * 64 + lane], __float_as_int(mx0));
    atomicMax((int*)&g_gmax[cur * 64 + lane + 32], __float_as_int(mx1));
    if (lane == 0) atomicAdd(&g_gcnt[cur], cnt);
}

// ---------------- MLP head (tiny, one block) ---------------------------------
__global__ void k_head(const float* __restrict__ cW1, const float* __restrict__ cb1,
                       const float* __restrict__ cW2, const float* __restrict__ cb2,
                       float* __restrict__ out) {
    __shared__ float z[NGRAPH * 128];
    int t = threadIdx.x;
    for (int idx = t; idx < NGRAPH * 128; idx += 256) {
        int g = idx >> 7, c = idx & 127;
        float v;
        if (c < 64) {
            int cnt = g_gcnt[g];
            v = g_gsum[g * 64 + c] / (float)max(cnt, 1);
        } else {
            v = g_gmax[g * 64 + (c - 64)];
        }
        z[idx] = v;
    }
    __syncthreads();
    for (int idx = t; idx < NGRAPH * 128; idx += 256) {
        int g = idx >> 7, o = idx & 127;
        float s = cb1[o];
        const float* wr = cW1 + o * 128;
        const float* zr = z + g * 128;
#pragma unroll 4
        for (int c = 0; c < 128; c++) s += zr[c] * wr[c];
        g_z2[idx] = fmaxf(s, 0.f);
    }
    __syncthreads();
    for (int idx = t; idx < NGRAPH * 2; idx += 256) {
        int g = idx >> 1, cls = idx & 1;
        float s = cb2[cls];
        const float* wr = cW2 + cls * 128;
        const float* zr = g_z2 + g * 128;
#pragma unroll 4
        for (int o = 0; o < 128; o++) s += zr[o] * wr[o];
        out[g * 2 + cls] = s;
    }
}

// ---------------- launcher ---------------------------------------------------
extern "C" void kernel_launch(void* const* d_in, const int* in_sizes, int n_in,
                              void* d_out, int out_size) {
    const float* x   = (const float*)d_in[0];
    const void*  ei  = d_in[1];
    const void*  bat = d_in[2];
    const float *Wl0 = (const float*)d_in[3],  *bl0 = (const float*)d_in[4],
                *Wr0 = (const float*)d_in[5],  *g0  = (const float*)d_in[6],
                *be0 = (const float*)d_in[7];
    const float *Wl1 = (const float*)d_in[8],  *bl1 = (const float*)d_in[9],
                *Wr1 = (const float*)d_in[10], *g1  = (const float*)d_in[11],
                *be1 = (const float*)d_in[12];
    const float *Wl2 = (const float*)d_in[13], *bl2 = (const float*)d_in[14],
                *Wr2 = (const float*)d_in[15], *g2  = (const float*)d_in[16],
                *be2 = (const float*)d_in[17];
    const float *cW1 = (const float*)d_in[18], *cb1 = (const float*)d_in[19],
                *cW2 = (const float*)d_in[20], *cb2 = (const float*)d_in[21];
    float* out = (float*)d_out;

    int Nn = in_sizes[2];          // 50000
    int E  = in_sizes[1] / 2;      // 600000

    float4 *agg4, *h14, *h24;
    cudaGetSymbolAddress((void**)&agg4, g_agg);
    cudaGetSymbolAddress((void**)&h14, g_h1);
    cudaGetSymbolAddress((void**)&h24, g_h2);
    float* agg = (float*)agg4;
    float* h1  = (float*)h14;
    float* h2  = (float*)h24;

    // probe index dtype, init, CSR build
    k_probe<<<1, 1>>>(ei, E, Nn);
    k_init<<<(Nn + 255) / 256, 256>>>(Nn);
    k_hist<<<(E + 255) / 256, 256>>>(ei, E, Nn);
    k_scan<<<1, 1024>>>(Nn);
    k_fill<<<(E + 255) / 256, 256>>>(ei, E, Nn);

    int aggBlocks = (Nn * 32 + 255) / 256;
    int gemmBlocks = (Nn + 127) / 128;

    // layer 0: in = x (128) -> h1 (128)
    k_agg<<<aggBlocks, 256>>>((const float4*)x, agg4, Nn);
    k_gemm_ln<128><<<gemmBlocks, 256>>>(agg, x, Wl0, Wr0, bl0, g0, be0, h1, Nn);
    // layer 1: in = h1 (128) -> h2 (128)
    k_agg<<<aggBlocks, 256>>>((const float4*)h1, agg4, Nn);
    k_gemm_ln<128><<<gemmBlocks, 256>>>(agg, h1, Wl1, Wr1, bl1, g1, be1, h2, Nn);
    // layer 2: in = h2 (128) -> h1 (64, reused)
    k_agg<<<aggBlocks, 256>>>((const float4*)h2, agg4, Nn);
    k_gemm_ln<64><<<gemmBlocks, 256>>>(agg, h2, Wl2, Wr2, bl2, g2, be2, h1, Nn);

    // pooling + head
    int poolWarps = (Nn + 63) / 64;
    k_pool<<<(poolWarps * 32 + 255) / 256, 256>>>(h1, bat, Nn);
    k_head<<<1, 256>>>(cW1, cb1, cW2, cb2, out);
}

// round 4
// speedup vs baseline: 1.1450x; 1.1450x over previous
#include <cuda_runtime.h>
#include <math.h>

#define LN_EPS 1e-5f
#define MAXN 50048
#define MAXE 600064
#define NGRAPH 64
#define NBLK_SCAN 256

// ---------------- scratch (device globals; 16B-aligned via float4) ----------
__device__ int    g_mode64;            // 1 if index inputs are int64, 0 if int32
__device__ int    g_deg[MAXN];
__device__ int    g_off[MAXN];
__device__ int    g_cursor[MAXN];
__device__ int    g_csr[MAXE];
__device__ int    g_bsum[NBLK_SCAN];
__device__ float4 g_agg[(size_t)MAXN * 32];   // 128 floats per node
__device__ float4 g_h1 [(size_t)MAXN * 32];
__device__ float4 g_h2 [(size_t)MAXN * 32];
__device__ float  g_gsum[NGRAPH * 64];
__device__ float  g_gmax[NGRAPH * 64];
__device__ int    g_gcnt[NGRAPH];
__device__ float  g_z2[NGRAPH * 128];

// ---------------- packed f32x2 helpers ---------------------------------------
__device__ __forceinline__ void fma2(unsigned long long& d, unsigned long long a,
                                     unsigned long long b) {
    asm("fma.rn.f32x2 %0, %1, %2, %0;" : "+l"(d) : "l"(a), "l"(b));
}
__device__ __forceinline__ unsigned long long dup2(float a) {
    unsigned long long r;
    asm("mov.b64 %0, {%1, %1};" : "=l"(r) : "f"(a));
    return r;
}
__device__ __forceinline__ void unpack2(unsigned long long u, float& lo, float& hi) {
    asm("mov.b64 {%0, %1}, %2;" : "=f"(lo), "=f"(hi) : "l"(u));
}

__device__ __forceinline__ int load_idx(const void* p, size_t i) {
    if (g_mode64) return (int)((const long long*)p)[i];
    return ((const int*)p)[i];
}

// ---------------- init (+ index dtype probe on thread 0) --------------------
__global__ void k_init(const void* ei, int E, int Nn) {
    int i = blockIdx.x * blockDim.x + threadIdx.x;
    if (i == 0) {
        const long long* e64 = (const long long*)ei;
        bool ok64 = true;
        for (int k = 0; k < 8; k++) {
            long long s = e64[k];
            long long d = e64[(size_t)E + k];
            if (s < 0 || s >= Nn || d < 0 || d >= Nn) ok64 = false;
        }
        g_mode64 = ok64 ? 1 : 0;
    }
    if (i < Nn) g_deg[i] = 0;
    if (i < NGRAPH * 64) { g_gsum[i] = 0.f; g_gmax[i] = 0.f; }
    if (i < NGRAPH) g_gcnt[i] = 0;
}

// ---------------- CSR build --------------------------------------------------
__global__ void k_hist(const void* __restrict__ ei, int E, int Nn) {
    int e = blockIdx.x * blockDim.x + threadIdx.x;
    if (e >= E) return;
    int dst = load_idx(ei, (size_t)E + e);
    if (dst >= 0 && dst < Nn) atomicAdd(&g_deg[dst], 1);
}

// decoupled 3-phase scan ------------------------------------------------------
__global__ void k_scanA(int Nn) {
    __shared__ int wsum[8];
    int b = blockIdx.x;
    int t = threadIdx.x;
    int i = b * 256 + t;
    int v = (i < Nn) ? g_deg[i] : 0;
#pragma unroll
    for (int o = 16; o; o >>= 1) v += __shfl_down_sync(0xffffffffu, v, o);
    if ((t & 31) == 0) wsum[t >> 5] = v;
    __syncthreads();
    if (t < 8) {
        int s = wsum[t];
#pragma unroll
        for (int o = 4; o; o >>= 1) s += __shfl_down_sync(0xffu, s, o);
        if (t == 0) g_bsum[b] = s;
    }
}

__global__ void k_scanB(int nblk) {
    __shared__ int sh[NBLK_SCAN];
    int t = threadIdx.x;
    int v = (t < nblk) ? g_bsum[t] : 0;
    sh[t] = v;
    __syncthreads();
    for (int d = 1; d < NBLK_SCAN; d <<= 1) {
        int u = (t >= d) ? sh[t - d] : 0;
        __syncthreads();
        sh[t] += u;
        __syncthreads();
    }
    g_bsum[t] = (t == 0) ? 0 : sh[t - 1];   // exclusive
}

__global__ void k_scanC(int Nn) {
    __shared__ int wsum[8];
    int b = blockIdx.x;
    int t = threadIdx.x;
    int i = b * 256 + t;
    int lane = t & 31, w = t >> 5;
    int v = (i < Nn) ? g_deg[i] : 0;
    int x = v;
#pragma unroll
    for (int o = 1; o < 32; o <<= 1) {
        int u = __shfl_up_sync(0xffffffffu, x, o);
        if (lane >= o) x += u;
    }
    if (lane == 31) wsum[w] = x;
    __syncthreads();
    if (t < 8) {
        int s = wsum[t];
        int y = s;
#pragma unroll
        for (int o = 1; o < 8; o <<= 1) {
            int u = __shfl_up_sync(0xffu, y, o);
            if (t >= o) y += u;
        }
        wsum[t] = y - s;    // exclusive warp offset
    }
    __syncthreads();
    int excl = (x - v) + wsum[w] + g_bsum[b];
    if (i < Nn) { g_off[i] = excl; g_cursor[i] = excl; }
}

__global__ void k_fill(const void* __restrict__ ei, int E, int Nn) {
    int e = blockIdx.x * blockDim.x + threadIdx.x;
    if (e >= E) return;
    int src = load_idx(ei, (size_t)e);
    int dst = load_idx(ei, (size_t)E + e);
    if (src < 0 || src >= Nn || dst < 0 || dst >= Nn) return;
    int p = atomicAdd(&g_cursor[dst], 1);
    if (p >= 0 && p < MAXE) g_csr[p] = src;
}

// ---------------- mean aggregation: one warp per node -----------------------
__global__ void k_agg(const float4* __restrict__ xin, float4* __restrict__ agg, int Nn) {
    int w = (blockIdx.x * blockDim.x + threadIdx.x) >> 5;
    int lane = threadIdx.x & 31;
    if (w >= Nn) return;
    int s = g_off[w];
    int d = g_deg[w];
    float4 acc = make_float4(0.f, 0.f, 0.f, 0.f);
    int e = 0;
    for (; e + 1 < d; e += 2) {
        int j0 = g_csr[s + e];
        int j1 = g_csr[s + e + 1];
        float4 v0 = __ldg(xin + (size_t)j0 * 32 + lane);
        float4 v1 = __ldg(xin + (size_t)j1 * 32 + lane);
        acc.x += v0.x; acc.y += v0.y; acc.z += v0.z; acc.w += v0.w;
        acc.x += v1.x; acc.y += v1.y; acc.z += v1.z; acc.w += v1.w;
    }
    if (e < d) {
        int j = g_csr[s + e];
        float4 v = __ldg(xin + (size_t)j * 32 + lane);
        acc.x += v.x; acc.y += v.y; acc.z += v.z; acc.w += v.w;
    }
    float inv = (d > 0) ? (1.f / (float)d) : 0.f;
    acc.x *= inv; acc.y *= inv; acc.z *= inv; acc.w *= inv;
    agg[(size_t)w * 32 + lane] = acc;
}

// ---------------- fused GEMM + bias + LayerNorm + ReLU ----------------------
// f32x2 packed-FMA inner loop. acc pairs in N (j) direction.
template <int TN>
__global__ void __launch_bounds__(256) k_gemm_ln(
    const float* __restrict__ agg, const float* __restrict__ xin,
    const float* __restrict__ Wl, const float* __restrict__ Wr,
    const float* __restrict__ bl, const float* __restrict__ gm,
    const float* __restrict__ bt, float* __restrict__ out, int Nn)
{
    constexpr int BM = 128;
    constexpr int BK = 16;
    constexpr int W  = TN / 16;      // 8 or 4
    constexpr int WP = W / 2;        // f32x2 pairs: 4 or 2
    constexpr int APAD = BM + 4;
    constexpr int BPAD = TN + 4;

    __shared__ float As[BK][APAD];
    __shared__ float Bs[BK][BPAD];
    __shared__ float2 red[BM * 16];

    int tid = threadIdx.x;
    int tx = tid & 15;
    int ty = tid >> 4;
    int m0 = blockIdx.x * BM;

    unsigned long long acc[8][WP];
#pragma unroll
    for (int i = 0; i < 8; i++)
#pragma unroll
        for (int j = 0; j < WP; j++) acc[i][j] = 0ull;

    for (int k0 = 0; k0 < 256; k0 += BK) {
        const float4* Asrc4 = (const float4*)((k0 < 128) ? agg : xin);
        const float4* Wsrc4 = (const float4*)((k0 < 128) ? Wl : Wr);
        int kb4 = (k0 & 127) >> 2;
        // A tile: 128 x 16 floats = 512 float4, 2 per thread
#pragma unroll
        for (int j = 0; j < 2; j++) {
            int f = tid + j * 256;
            int m = f >> 2, q = f & 3;
            int node = m0 + m;
            float4 v = make_float4(0.f, 0.f, 0.f, 0.f);
            if (node < Nn) v = __ldg(Asrc4 + (size_t)node * 32 + kb4 + q);
            As[q * 4 + 0][m] = v.x;
            As[q * 4 + 1][m] = v.y;
            As[q * 4 + 2][m] = v.z;
            As[q * 4 + 3][m] = v.w;
        }
        // B tile: TN x 16 floats = TN*4 float4
#pragma unroll
        for (int j = 0; j < (TN * 4) / 256; j++) {
            int f = tid + j * 256;
            int o = f >> 2, q = f & 3;
            float4 v = __ldg(Wsrc4 + (size_t)o * 32 + kb4 + q);
            Bs[q * 4 + 0][o] = v.x;
            Bs[q * 4 + 1][o] = v.y;
            Bs[q * 4 + 2][o] = v.z;
            Bs[q * 4 + 3][o] = v.w;
        }
        __syncthreads();
#pragma unroll
        for (int kk = 0; kk < BK; kk++) {
            unsigned long long a2[8];
#pragma unroll
            for (int i = 0; i < 8; i++) a2[i] = dup2(As[kk][ty * 8 + i]);
            unsigned long long b2[WP];
#pragma unroll
            for (int j = 0; j < WP; j++)
                b2[j] = *(const unsigned long long*)&Bs[kk][tx * W + 2 * j];
#pragma unroll
            for (int i = 0; i < 8; i++)
#pragma unroll
                for (int j = 0; j < WP; j++) fma2(acc[i][j], a2[i], b2[j]);
        }
        __syncthreads();
    }

    // unpack accumulators, add bias
    float av[8][W];
    float blv[W], gv[W], bv[W];
#pragma unroll
    for (int j = 0; j < W; j++) {
        int o = tx * W + j;
        blv[j] = bl[o];
        gv[j]  = gm[o];
        bv[j]  = bt[o];
    }
#pragma unroll
    for (int i = 0; i < 8; i++)
#pragma unroll
        for (int j = 0; j < WP; j++) {
            float lo, hi;
            unpack2(acc[i][j], lo, hi);
            av[i][2 * j]     = lo + blv[2 * j];
            av[i][2 * j + 1] = hi + blv[2 * j + 1];
        }

    // LN row reduction
#pragma unroll
    for (int i = 0; i < 8; i++) {
        float s = 0.f, s2 = 0.f;
#pragma unroll
        for (int j = 0; j < W; j++) {
            s += av[i][j];
            s2 += av[i][j] * av[i][j];
        }
        red[(ty * 8 + i) * 16 + tx] = make_float2(s, s2);
    }
    __syncthreads();

#pragma unroll
    for (int i = 0; i < 8; i++) {
        int row = ty * 8 + i;
        float s = 0.f, s2 = 0.f;
#pragma unroll
        for (int t = 0; t < 16; t++) {
            float2 v = red[row * 16 + t];
            s += v.x;
            s2 += v.y;
        }
        float mu = s * (1.f / (float)TN);
        float var = s2 * (1.f / (float)TN) - mu * mu;
        float rinv = rsqrtf(var + LN_EPS);
        int node = m0 + row;
        if (node < Nn) {
            float ov[W];
#pragma unroll
            for (int j = 0; j < W; j++) {
                float val = (av[i][j] - mu) * rinv * gv[j] + bv[j];
                ov[j] = fmaxf(val, 0.f);
            }
            float* op = out + (size_t)node * TN + tx * W;
#pragma unroll
            for (int j = 0; j < W; j += 4)
                *(float4*)(op + j) = make_float4(ov[j], ov[j + 1], ov[j + 2], ov[j + 3]);
        }
    }
}

// ---------------- graph pooling: mean + max over sorted batch ---------------
__global__ void k_pool(const float* __restrict__ h, const void* __restrict__ batch, int Nn) {
    const int NPW = 64;
    int w = (blockIdx.x * blockDim.x + threadIdx.x) >> 5;
    int lane = threadIdx.x & 31;
    int start = w * NPW;
    if (start >= Nn) return;
    int end = min(start + NPW, Nn);

    float s0 = 0.f, s1 = 0.f, mx0 = 0.f, mx1 = 0.f;
    int cur = load_idx(batch, (size_t)start);
    if (cur < 0) cur = 0;
    if (cur >= NGRAPH) cur = NGRAPH - 1;
    int cnt = 0;
    for (int i = start; i < end; i++) {
        int g = load_idx(batch, (size_t)i);
        if (g < 0) g = 0;
        if (g >= NGRAPH) g = NGRAPH - 1;
        if (g != cur) {
            atomicAdd(&g_gsum[cur * 64 + lane], s0);
            atomicAdd(&g_gsum[cur * 64 + lane + 32], s1);
            atomicMax((int*)&g_gmax[cur * 64 + lane], __float_as_int(mx0));
            atomicMax((int*)&g_gmax[cur * 64 + lane + 32], __float_as_int(mx1));
            if (lane == 0) atomicAdd(&g_gcnt[cur], cnt);
            s0 = s1 = mx0 = mx1 = 0.f;
            cnt = 0;
            cur = g;
        }
        float v0 = h[(size_t)i * 64 + lane];
        float v1 = h[(size_t)i * 64 + lane + 32];
        s0 += v0; s1 += v1;
        mx0 = fmaxf(mx0, v0);
        mx1 = fmaxf(mx1, v1);
        cnt++;
    }
    atomicAdd(&g_gsum[cur * 64 + lane], s0);
    atomicAdd(&g_gsum[cur * 64 + lane + 32], s1);
    atomicMax((int*)&g_gmax[cur * 64 + lane], __float_as_int(mx0));
    atomicMax((int*)&g_gmax[cur * 64 + lane + 32], __float_as_int(mx1));
    if (lane == 0) atomicAdd(&g_gcnt[cur], cnt);
}

// ---------------- MLP head (tiny, one block) ---------------------------------
__global__ void k_head(const float* __restrict__ cW1, const float* __restrict__ cb1,
                       const float* __restrict__ cW2, const float* __restrict__ cb2,
                       float* __restrict__ out) {
    __shared__ float z[NGRAPH * 128];
    int t = threadIdx.x;
    for (int idx = t; idx < NGRAPH * 128; idx += 256) {
        int g = idx >> 7, c = idx & 127;
        float v;
        if (c < 64) {
            int cnt = g_gcnt[g];
            v = g_gsum[g * 64 + c] / (float)max(cnt, 1);
        } else {
            v = g_gmax[g * 64 + (c - 64)];
        }
        z[idx] = v;
    }
    __syncthreads();
    for (int idx = t; idx < NGRAPH * 128; idx += 256) {
        int g = idx >> 7, o = idx & 127;
        float s = cb1[o];
        const float* wr = cW1 + o * 128;
        const float* zr = z + g * 128;
#pragma unroll 4
        for (int c = 0; c < 128; c++) s += zr[c] * wr[c];
        g_z2[idx] = fmaxf(s, 0.f);
    }
    __syncthreads();
    for (int idx = t; idx < NGRAPH * 2; idx += 256) {
        int g = idx >> 1, cls = idx & 1;
        float s = cb2[cls];
        const float* wr = cW2 + cls * 128;
        const float* zr = g_z2 + g * 128;
#pragma unroll 4
        for (int o = 0; o < 128; o++) s += zr[o] * wr[o];
        out[g * 2 + cls] = s;
    }
}

// ---------------- launcher ---------------------------------------------------
extern "C" void kernel_launch(void* const* d_in, const int* in_sizes, int n_in,
                              void* d_out, int out_size) {
    const float* x   = (const float*)d_in[0];
    const void*  ei  = d_in[1];
    const void*  bat = d_in[2];
    const float *Wl0 = (const float*)d_in[3],  *bl0 = (const float*)d_in[4],
                *Wr0 = (const float*)d_in[5],  *g0  = (const float*)d_in[6],
                *be0 = (const float*)d_in[7];
    const float *Wl1 = (const float*)d_in[8],  *bl1 = (const float*)d_in[9],
                *Wr1 = (const float*)d_in[10], *g1  = (const float*)d_in[11],
                *be1 = (const float*)d_in[12];
    const float *Wl2 = (const float*)d_in[13], *bl2 = (const float*)d_in[14],
                *Wr2 = (const float*)d_in[15], *g2  = (const float*)d_in[16],
                *be2 = (const float*)d_in[17];
    const float *cW1 = (const float*)d_in[18], *cb1 = (const float*)d_in[19],
                *cW2 = (const float*)d_in[20], *cb2 = (const float*)d_in[21];
    float* out = (float*)d_out;

    int Nn = in_sizes[2];          // 50000
    int E  = in_sizes[1] / 2;      // 600000

    float4 *agg4, *h14, *h24;
    cudaGetSymbolAddress((void**)&agg4, g_agg);
    cudaGetSymbolAddress((void**)&h14, g_h1);
    cudaGetSymbolAddress((void**)&h24, g_h2);
    float* agg = (float*)agg4;
    float* h1  = (float*)h14;
    float* h2  = (float*)h24;

    int nblk = (Nn + 255) / 256;

    // init (+probe) + CSR build
    k_init<<<(Nn + 255) / 256, 256>>>(ei, E, Nn);
    k_hist<<<(E + 255) / 256, 256>>>(ei, E, Nn);
    k_scanA<<<nblk, 256>>>(Nn);
    k_scanB<<<1, NBLK_SCAN>>>(nblk);
    k_scanC<<<nblk, 256>>>(Nn);
    k_fill<<<(E + 255) / 256, 256>>>(ei, E, Nn);

    int aggBlocks = (Nn * 32 + 255) / 256;
    int gemmBlocks = (Nn + 127) / 128;

    // layer 0: in = x (128) -> h1 (128)
    k_agg<<<aggBlocks, 256>>>((const float4*)x, agg4, Nn);
    k_gemm_ln<128><<<gemmBlocks, 256>>>(agg, x, Wl0, Wr0, bl0, g0, be0, h1, Nn);
    // layer 1: in = h1 (128) -> h2 (128)
    k_agg<<<aggBlocks, 256>>>((const float4*)h1, agg4, Nn);
    k_gemm_ln<128><<<gemmBlocks, 256>>>(agg, h1, Wl1, Wr1, bl1, g1, be1, h2, Nn);
    // layer 2: in = h2 (128) -> h1 (64, reused)
    k_agg<<<aggBlocks, 256>>>((const float4*)h2, agg4, Nn);
    k_gemm_ln<64><<<gemmBlocks, 256>>>(agg, h2, Wl2, Wr2, bl2, g2, be2, h1, Nn);

    // pooling + head
    int poolWarps = (Nn + 63) / 64;
    k_pool<<<(poolWarps * 32 + 255) / 256, 256>>>(h1, bat, Nn);
    k_head<<<1, 256>>>(cW1, cb1, cW2, cb2, out);
}

// round 8
// speedup vs baseline: 1.2953x; 1.1313x over previous
#include <cuda_runtime.h>
#include <cuda_bf16.h>
#include <cstdint>
#include <math.h>

#define LN_EPS 1e-5f
#define MAXN 50048
#define MAXE 600064
#define NGRAPH 64
#define NBLK_SCAN 256

// ---------------- scratch (device globals) ----------------------------------
__device__ int    g_mode64;
__device__ int    g_deg[MAXN];
__device__ int    g_off[MAXN];
__device__ int    g_cursor[MAXN];
__device__ int    g_csr[MAXE];
__device__ int    g_bsum[NBLK_SCAN];
__device__ float4 g_agg[(size_t)MAXN * 32];
__device__ float4 g_h1 [(size_t)MAXN * 32];
__device__ float4 g_h2 [(size_t)MAXN * 32];
__device__ float  g_gsum[NGRAPH * 64];
__device__ float  g_gmax[NGRAPH * 64];
__device__ int    g_gcnt[NGRAPH];
__device__ float  g_z2[NGRAPH * 128];
// bf16 weight images, plain row-major [o][k]: [layer(3)][chunk(2)] x (hi 32KB + lo 32KB)
__device__ __align__(16) unsigned char g_wimg[3 * 4 * 32768];

__device__ __forceinline__ int load_idx(const void* p, size_t i) {
    if (g_mode64) return (int)((const long long*)p)[i];
    return ((const int*)p)[i];
}

// bf16 mma m16n8k16: d += a * b (A row-major m16k16, B col-major k16n8)
__device__ __forceinline__ void mma16816(float* d, const uint32_t* a, const uint32_t* b) {
    asm volatile(
        "mma.sync.aligned.m16n8k16.row.col.f32.bf16.bf16.f32 "
        "{%0,%1,%2,%3}, {%4,%5,%6,%7}, {%8,%9}, {%0,%1,%2,%3};"
        : "+f"(d[0]), "+f"(d[1]), "+f"(d[2]), "+f"(d[3])
        : "r"(a[0]), "r"(a[1]), "r"(a[2]), "r"(a[3]), "r"(b[0]), "r"(b[1]));
}

// ---------------- init (+ index dtype probe) ---------------------------------
__global__ void k_init(const void* ei, int E, int Nn) {
    int i = blockIdx.x * blockDim.x + threadIdx.x;
    if (i == 0) {
        const long long* e64 = (const long long*)ei;
        bool ok64 = true;
        for (int k = 0; k < 8; k++) {
            long long s = e64[k];
            long long d = e64[(size_t)E + k];
            if (s < 0 || s >= Nn || d < 0 || d >= Nn) ok64 = false;
        }
        g_mode64 = ok64 ? 1 : 0;
    }
    if (i < Nn) g_deg[i] = 0;
    if (i < NGRAPH * 64) { g_gsum[i] = 0.f; g_gmax[i] = 0.f; }
    if (i < NGRAPH) g_gcnt[i] = 0;
}

// ---------------- weight prep: fp32 -> bf16 hi/lo row-major images ----------
struct WPtrs { const float* w[6]; };

__global__ void k_prep(WPtrs wp) {
    int lc = blockIdx.y;           // 0..5 : layer*2 + chunk
    int tn = ((lc >> 1) == 2) ? 64 : 128;
    int idx = blockIdx.x * blockDim.x + threadIdx.x;   // 0..16383
    int o = idx >> 7, k = idx & 127;
    if (o >= tn) return;
    float v = wp.w[lc][o * 128 + k];
    __nv_bfloat16 hi = __float2bfloat16(v);
    __nv_bfloat16 lo = __float2bfloat16(v - __bfloat162float(hi));
    unsigned char* base = g_wimg + (size_t)lc * 65536;
    ((unsigned short*)base)[o * 128 + k]           = __bfloat16_as_ushort(hi);
    ((unsigned short*)(base + 32768))[o * 128 + k] = __bfloat16_as_ushort(lo);
}

// ---------------- CSR build --------------------------------------------------
__global__ void k_hist(const void* __restrict__ ei, int E, int Nn) {
    int e = blockIdx.x * blockDim.x + threadIdx.x;
    if (e >= E) return;
    int dst = load_idx(ei, (size_t)E + e);
    if (dst >= 0 && dst < Nn) atomicAdd(&g_deg[dst], 1);
}

__global__ void k_scanA(int Nn) {
    __shared__ int wsum[8];
    int b = blockIdx.x, t = threadIdx.x;
    int i = b * 256 + t;
    int v = (i < Nn) ? g_deg[i] : 0;
#pragma unroll
    for (int o = 16; o; o >>= 1) v += __shfl_down_sync(0xffffffffu, v, o);
    if ((t & 31) == 0) wsum[t >> 5] = v;
    __syncthreads();
    if (t < 8) {
        int s = wsum[t];
#pragma unroll
        for (int o = 4; o; o >>= 1) s += __shfl_down_sync(0xffu, s, o);
        if (t == 0) g_bsum[b] = s;
    }
}

__global__ void k_scanB(int nblk) {
    __shared__ int sh[NBLK_SCAN];
    int t = threadIdx.x;
    int v = (t < nblk) ? g_bsum[t] : 0;
    sh[t] = v;
    __syncthreads();
    for (int d = 1; d < NBLK_SCAN; d <<= 1) {
        int u = (t >= d) ? sh[t - d] : 0;
        __syncthreads();
        sh[t] += u;
        __syncthreads();
    }
    g_bsum[t] = (t == 0) ? 0 : sh[t - 1];
}

__global__ void k_scanC(int Nn) {
    __shared__ int wsum[8];
    int b = blockIdx.x, t = threadIdx.x;
    int i = b * 256 + t;
    int lane = t & 31, w = t >> 5;
    int v = (i < Nn) ? g_deg[i] : 0;
    int x = v;
#pragma unroll
    for (int o = 1; o < 32; o <<= 1) {
        int u = __shfl_up_sync(0xffffffffu, x, o);
        if (lane >= o) x += u;
    }
    if (lane == 31) wsum[w] = x;
    __syncthreads();
    if (t < 8) {
        int s = wsum[t];
        int y = s;
#pragma unroll
        for (int o = 1; o < 8; o <<= 1) {
            int u = __shfl_up_sync(0xffu, y, o);
            if (t >= o) y += u;
        }
        wsum[t] = y - s;
    }
    __syncthreads();
    int excl = (x - v) + wsum[w] + g_bsum[b];
    if (i < Nn) { g_off[i] = excl; g_cursor[i] = excl; }
}

__global__ void k_fill(const void* __restrict__ ei, int E, int Nn) {
    int e = blockIdx.x * blockDim.x + threadIdx.x;
    if (e >= E) return;
    int src = load_idx(ei, (size_t)e);
    int dst = load_idx(ei, (size_t)E + e);
    if (src < 0 || src >= Nn || dst < 0 || dst >= Nn) return;
    int p = atomicAdd(&g_cursor[dst], 1);
    if (p >= 0 && p < MAXE) g_csr[p] = src;
}

// ---------------- mean aggregation: one warp per node, MLP=4 ----------------
__global__ void k_agg(const float4* __restrict__ xin, float4* __restrict__ agg, int Nn) {
    int w = (blockIdx.x * blockDim.x + threadIdx.x) >> 5;
    int lane = threadIdx.x & 31;
    if (w >= Nn) return;
    int s = g_off[w];
    int d = g_deg[w];
    float4 acc = make_float4(0.f, 0.f, 0.f, 0.f);
    int e = 0;
    for (; e + 3 < d; e += 4) {
        int j0 = g_csr[s + e], j1 = g_csr[s + e + 1];
        int j2 = g_csr[s + e + 2], j3 = g_csr[s + e + 3];
        float4 v0 = __ldg(xin + (size_t)j0 * 32 + lane);
        float4 v1 = __ldg(xin + (size_t)j1 * 32 + lane);
        float4 v2 = __ldg(xin + (size_t)j2 * 32 + lane);
        float4 v3 = __ldg(xin + (size_t)j3 * 32 + lane);
        acc.x += v0.x + v1.x + v2.x + v3.x;
        acc.y += v0.y + v1.y + v2.y + v3.y;
        acc.z += v0.z + v1.z + v2.z + v3.z;
        acc.w += v0.w + v1.w + v2.w + v3.w;
    }
    for (; e < d; e++) {
        int j = g_csr[s + e];
        float4 v = __ldg(xin + (size_t)j * 32 + lane);
        acc.x += v.x; acc.y += v.y; acc.z += v.z; acc.w += v.w;
    }
    float inv = (d > 0) ? (1.f / (float)d) : 0.f;
    acc.x *= inv; acc.y *= inv; acc.z *= inv; acc.w *= inv;
    agg[(size_t)w * 32 + lane] = acc;
}

// ---------------- HMMA GEMM + bias + LayerNorm + ReLU ------------------------
// D[128, TN] = [agg | xin](128x256) @ W^T with bf16 hi/lo split (3 mma terms).
// Block: 128 rows, 8 warps x 16 rows. K staged in 4 chunks of 64.
template <int TN>
__global__ void __launch_bounds__(256) k_gemm_mma(
    const float4* __restrict__ agg, const float4* __restrict__ xin,
    const unsigned char* __restrict__ wimg,
    const float* __restrict__ bl, const float* __restrict__ gm,
    const float* __restrict__ bt, float* __restrict__ out, int Nn)
{
    constexpr int NT = TN / 8;           // n-tiles per warp
    constexpr int AS = 72;               // smem row stride in bf16
    constexpr int A_HI = 0;
    constexpr int A_LO = 128 * AS * 2;                 // 18432 B
    constexpr int B_HI = 2 * A_LO;                     // 36864 B
    constexpr int B_LO = B_HI + TN * AS * 2;
    constexpr int BIAS = B_HI + 2 * TN * AS * 2;
    constexpr int STGS = TN + 4;         // output stage stride (floats)

    extern __shared__ char sm[];
    __nv_bfloat16* ah = (__nv_bfloat16*)(sm + A_HI);
    __nv_bfloat16* al = (__nv_bfloat16*)(sm + A_LO);
    __nv_bfloat16* bh = (__nv_bfloat16*)(sm + B_HI);
    __nv_bfloat16* bq = (__nv_bfloat16*)(sm + B_LO);

    int tid = threadIdx.x;
    int w = tid >> 5, lane = tid & 31;
    int gr = lane >> 2, tig = lane & 3;
    int m0 = blockIdx.x * 128;

    if (tid < TN) {
        ((float*)(sm + BIAS))[tid]          = bl[tid];
        ((float*)(sm + BIAS))[TN + tid]     = gm[tid];
        ((float*)(sm + BIAS))[2 * TN + tid] = bt[tid];
    }

    float acc[NT][4];
#pragma unroll
    for (int n = 0; n < NT; n++)
#pragma unroll
        for (int j = 0; j < 4; j++) acc[n][j] = 0.f;

    for (int c = 0; c < 4; c++) {
        const float4* src = (c < 2) ? agg : xin;
        int q0 = (c & 1) * 16;           // float4 col offset within 128-float row
        __syncthreads();                  // prior chunk's smem reads done
        // stage A chunk: 128 rows x 64 k (fp32 -> bf16 hi/lo)
#pragma unroll
        for (int i = 0; i < 8; i++) {
            int idx = tid + i * 256;      // 0..2047
            int row = idx >> 4, q = idx & 15;
            int node = m0 + row;
            float4 v = make_float4(0.f, 0.f, 0.f, 0.f);
            if (node < Nn) v = __ldg(src + (size_t)node * 32 + q0 + q);
            __nv_bfloat16 h0 = __float2bfloat16(v.x);
            __nv_bfloat16 h1 = __float2bfloat16(v.y);
            __nv_bfloat16 h2 = __float2bfloat16(v.z);
            __nv_bfloat16 h3 = __float2bfloat16(v.w);
            __nv_bfloat16 l0 = __float2bfloat16(v.x - __bfloat162float(h0));
            __nv_bfloat16 l1 = __float2bfloat16(v.y - __bfloat162float(h1));
            __nv_bfloat16 l2 = __float2bfloat16(v.z - __bfloat162float(h2));
            __nv_bfloat16 l3 = __float2bfloat16(v.w - __bfloat162float(h3));
            int doff = row * AS + q * 4;
            *(ushort4*)(ah + doff) = make_ushort4(
                __bfloat16_as_ushort(h0), __bfloat16_as_ushort(h1),
                __bfloat16_as_ushort(h2), __bfloat16_as_ushort(h3));
            *(ushort4*)(al + doff) = make_ushort4(
                __bfloat16_as_ushort(l0), __bfloat16_as_ushort(l1),
                __bfloat16_as_ushort(l2), __bfloat16_as_ushort(l3));
        }
        // stage B chunk: TN rows x 64 k from prebuilt bf16 images
        {
            int half = c >> 1;           // 0 = Wl, 1 = Wr
            const ushort4* sh = (const ushort4*)(wimg + (size_t)half * 65536);
            const ushort4* sl = (const ushort4*)(wimg + (size_t)half * 65536 + 32768);
            int kq = (c & 1) * 16;       // ushort4 offset within 128-bf16 row
#pragma unroll
            for (int i = 0; i < (TN * 16) / 256; i++) {
                int idx = tid + i * 256;
                int row = idx >> 4, u = idx & 15;
                int soff = row * 32 + kq + u;
                int doff = row * AS + u * 4;
                *(ushort4*)(bh + doff) = __ldg(sh + soff);
                *(ushort4*)(bq + doff) = __ldg(sl + soff);
            }
        }
        __syncthreads();
        // compute: 4 k-steps of 16
#pragma unroll
        for (int ks = 0; ks < 4; ks++) {
            int abase = (w * 16 + gr) * AS + ks * 16 + tig * 2;
            uint32_t afh[4], afl[4];
            afh[0] = *(const uint32_t*)(ah + abase);
            afh[1] = *(const uint32_t*)(ah + abase + 8 * AS);
            afh[2] = *(const uint32_t*)(ah + abase + 8);
            afh[3] = *(const uint32_t*)(ah + abase + 8 * AS + 8);
            afl[0] = *(const uint32_t*)(al + abase);
            afl[1] = *(const uint32_t*)(al + abase + 8 * AS);
            afl[2] = *(const uint32_t*)(al + abase + 8);
            afl[3] = *(const uint32_t*)(al + abase + 8 * AS + 8);
#pragma unroll
            for (int nt = 0; nt < NT; nt++) {
                int bbase = (nt * 8 + gr) * AS + ks * 16 + tig * 2;
                uint32_t bfh[2], bfl[2];
                bfh[0] = *(const uint32_t*)(bh + bbase);
                bfh[1] = *(const uint32_t*)(bh + bbase + 8);
                bfl[0] = *(const uint32_t*)(bq + bbase);
                bfl[1] = *(const uint32_t*)(bq + bbase + 8);
                mma16816(acc[nt], afh, bfh);
                mma16816(acc[nt], afh, bfl);
                mma16816(acc[nt], afl, bfh);
            }
        }
    }
    __syncthreads();   // all mainloop smem reads done before stage overwrite

    // bias + LN stats (rows r0 = w*16+gr, r1 = r0+8)
    const float* sbl = (const float*)(sm + BIAS);
    const float* sgm = sbl + TN;
    const float* sbt = sbl + 2 * TN;
    float s0 = 0.f, q0s = 0.f, s1 = 0.f, q1s = 0.f;
#pragma unroll
    for (int nt = 0; nt < NT; nt++) {
        int col = nt * 8 + tig * 2;
        acc[nt][0] += sbl[col];     acc[nt][1] += sbl[col + 1];
        acc[nt][2] += sbl[col];     acc[nt][3] += sbl[col + 1];
        s0 += acc[nt][0] + acc[nt][1];
        q0s += acc[nt][0] * acc[nt][0] + acc[nt][1] * acc[nt][1];
        s1 += acc[nt][2] + acc[nt][3];
        q1s += acc[nt][2] * acc[nt][2] + acc[nt][3] * acc[nt][3];
    }
#pragma unroll
    for (int o = 1; o < 4; o <<= 1) {
        s0  += __shfl_xor_sync(0xffffffffu, s0, o);
        q0s += __shfl_xor_sync(0xffffffffu, q0s, o);
        s1  += __shfl_xor_sync(0xffffffffu, s1, o);
        q1s += __shfl_xor_sync(0xffffffffu, q1s, o);
    }
    float inv = 1.f / (float)TN;
    float mu0 = s0 * inv, var0 = q0s * inv - mu0 * mu0;
    float mu1 = s1 * inv, var1 = q1s * inv - mu1 * mu1;
    float r0v = rsqrtf(var0 + LN_EPS), r1v = rsqrtf(var1 + LN_EPS);

    // normalize + ReLU, stage to smem
    float* stage = (float*)(sm + A_HI);
    int r0 = w * 16 + gr, r1 = r0 + 8;
#pragma unroll
    for (int nt = 0; nt < NT; nt++) {
        int col = nt * 8 + tig * 2;
        stage[r0 * STGS + col]     = fmaxf((acc[nt][0] - mu0) * r0v * sgm[col]     + sbt[col],     0.f);
        stage[r0 * STGS + col + 1] = fmaxf((acc[nt][1] - mu0) * r0v * sgm[col + 1] + sbt[col + 1], 0.f);
        stage[r1 * STGS + col]     = fmaxf((acc[nt][2] - mu1) * r1v * sgm[col]     + sbt[col],     0.f);
        stage[r1 * STGS + col + 1] = fmaxf((acc[nt][3] - mu1) * r1v * sgm[col + 1] + sbt[col + 1], 0.f);
    }
    __syncthreads();

    // coalesced float4 store
    constexpr int NPF4 = TN / 4;
#pragma unroll
    for (int i = 0; i < (128 * NPF4) / 256; i++) {
        int idx = tid + i * 256;
        int row = idx / NPF4, q = idx % NPF4;
        int node = m0 + row;
        if (node < Nn)
            ((float4*)(out + (size_t)node * TN))[q] =
                *(float4*)&stage[row * STGS + q * 4];
    }
}

// ---------------- graph pooling ----------------------------------------------
__global__ void k_pool(const float* __restrict__ h, const void* __restrict__ batch, int Nn) {
    const int NPW = 64;
    int w = (blockIdx.x * blockDim.x + threadIdx.x) >> 5;
    int lane = threadIdx.x & 31;
    int start = w * NPW;
    if (start >= Nn) return;
    int end = min(start + NPW, Nn);

    float s0 = 0.f, s1 = 0.f, mx0 = 0.f, mx1 = 0.f;
    int cur = load_idx(batch, (size_t)start);
    if (cur < 0) cur = 0;
    if (cur >= NGRAPH) cur = NGRAPH - 1;
    int cnt = 0;
    for (int i = start; i < end; i++) {
        int g = load_idx(batch, (size_t)i);
        if (g < 0) g = 0;
        if (g >= NGRAPH) g = NGRAPH - 1;
        if (g != cur) {
            atomicAdd(&g_gsum[cur * 64 + lane], s0);
            atomicAdd(&g_gsum[cur * 64 + lane + 32], s1);
            atomicMax((int*)&g_gmax[cur * 64 + lane], __float_as_int(mx0));
            atomicMax((int*)&g_gmax[cur * 64 + lane + 32], __float_as_int(mx1));
            if (lane == 0) atomicAdd(&g_gcnt[cur], cnt);
            s0 = s1 = mx0 = mx1 = 0.f;
            cnt = 0;
            cur = g;
        }
        float v0 = h[(size_t)i * 64 + lane];
        float v1 = h[(size_t)i * 64 + lane + 32];
        s0 += v0; s1 += v1;
        mx0 = fmaxf(mx0, v0);
        mx1 = fmaxf(mx1, v1);
        cnt++;
    }
    atomicAdd(&g_gsum[cur * 64 + lane], s0);
    atomicAdd(&g_gsum[cur * 64 + lane + 32], s1);
    atomicMax((int*)&g_gmax[cur * 64 + lane], __float_as_int(mx0));
    atomicMax((int*)&g_gmax[cur * 64 + lane + 32], __float_as_int(mx1));
    if (lane == 0) atomicAdd(&g_gcnt[cur], cnt);
}

// ---------------- MLP head ----------------------------------------------------
__global__ void k_head(const float* __restrict__ cW1, const float* __restrict__ cb1,
                       const float* __restrict__ cW2, const float* __restrict__ cb2,
                       float* __restrict__ out) {
    __shared__ float z[NGRAPH * 128];
    int t = threadIdx.x;
    for (int idx = t; idx < NGRAPH * 128; idx += 256) {
        int g = idx >> 7, c = idx & 127;
        float v;
        if (c < 64) {
            int cnt = g_gcnt[g];
            v = g_gsum[g * 64 + c] / (float)max(cnt, 1);
        } else {
            v = g_gmax[g * 64 + (c - 64)];
        }
        z[idx] = v;
    }
    __syncthreads();
    for (int idx = t; idx < NGRAPH * 128; idx += 256) {
        int g = idx >> 7, o = idx & 127;
        float s = cb1[o];
        const float* wr = cW1 + o * 128;
        const float* zr = z + g * 128;
#pragma unroll 4
        for (int c = 0; c < 128; c++) s += zr[c] * wr[c];
        g_z2[idx] = fmaxf(s, 0.f);
    }
    __syncthreads();
    for (int idx = t; idx < NGRAPH * 2; idx += 256) {
        int g = idx >> 1, cls = idx & 1;
        float s = cb2[cls];
        const float* wr = cW2 + cls * 128;
        const float* zr = g_z2 + g * 128;
#pragma unroll 4
        for (int o = 0; o < 128; o++) s += zr[o] * wr[o];
        out[g * 2 + cls] = s;
    }
}

// ---------------- launcher ----------------------------------------------------
extern "C" void kernel_launch(void* const* d_in, const int* in_sizes, int n_in,
                              void* d_out, int out_size) {
    const float* x   = (const float*)d_in[0];
    const void*  ei  = d_in[1];
    const void*  bat = d_in[2];
    const float *Wl0 = (const float*)d_in[3],  *bl0 = (const float*)d_in[4],
                *Wr0 = (const float*)d_in[5],  *g0  = (const float*)d_in[6],
                *be0 = (const float*)d_in[7];
    const float *Wl1 = (const float*)d_in[8],  *bl1 = (const float*)d_in[9],
                *Wr1 = (const float*)d_in[10], *g1  = (const float*)d_in[11],
                *be1 = (const float*)d_in[12];
    const float *Wl2 = (const float*)d_in[13], *bl2 = (const float*)d_in[14],
                *Wr2 = (const float*)d_in[15], *g2  = (const float*)d_in[16],
                *be2 = (const float*)d_in[17];
    const float *cW1 = (const float*)d_in[18], *cb1 = (const float*)d_in[19],
                *cW2 = (const float*)d_in[20], *cb2 = (const float*)d_in[21];
    float* out = (float*)d_out;

    int Nn = in_sizes[2];          // 50000
    int E  = in_sizes[1] / 2;      // 600000

    float4 *agg4, *h14, *h24;
    unsigned char* wimg;
    cudaGetSymbolAddress((void**)&agg4, g_agg);
    cudaGetSymbolAddress((void**)&h14, g_h1);
    cudaGetSymbolAddress((void**)&h24, g_h2);
    cudaGetSymbolAddress((void**)&wimg, g_wimg);
    float* h1 = (float*)h14;
    float* h2 = (float*)h24;

    // smem: A(2x18432) + B(2xTN*144) + bias(3*TN*4)
    int smem128 = 36864 + 2 * 128 * 144 + 3 * 128 * 4;   // 75264
    int smem64  = 36864 + 2 * 64 * 144  + 3 * 64 * 4;    // 56064
    cudaFuncSetAttribute(k_gemm_mma<128>, cudaFuncAttributeMaxDynamicSharedMemorySize, smem128);
    cudaFuncSetAttribute(k_gemm_mma<64>,  cudaFuncAttributeMaxDynamicSharedMemorySize, smem64);

    int nblk = (Nn + 255) / 256;

    k_init<<<nblk, 256>>>(ei, E, Nn);
    WPtrs wp;
    wp.w[0] = Wl0; wp.w[1] = Wr0;
    wp.w[2] = Wl1; wp.w[3] = Wr1;
    wp.w[4] = Wl2; wp.w[5] = Wr2;
    k_prep<<<dim3(64, 6), 256>>>(wp);
    k_hist<<<(E + 255) / 256, 256>>>(ei, E, Nn);
    k_scanA<<<nblk, 256>>>(Nn);
    k_scanB<<<1, NBLK_SCAN>>>(nblk);
    k_scanC<<<nblk, 256>>>(Nn);
    k_fill<<<(E + 255) / 256, 256>>>(ei, E, Nn);

    int aggBlocks = (Nn * 32 + 255) / 256;
    int gemmBlocks = (Nn + 127) / 128;

    // layer 0: in = x -> h1 (128)
    k_agg<<<aggBlocks, 256>>>((const float4*)x, agg4, Nn);
    k_gemm_mma<128><<<gemmBlocks, 256, smem128>>>(agg4, (const float4*)x,
        wimg + 0 * 131072, bl0, g0, be0, h1, Nn);
    // layer 1: h1 -> h2 (128)
    k_agg<<<aggBlocks, 256>>>((const float4*)h1, agg4, Nn);
    k_gemm_mma<128><<<gemmBlocks, 256, smem128>>>(agg4, (const float4*)h1,
        wimg + 1 * 131072, bl1, g1, be1, h2, Nn);
    // layer 2: h2 -> h1 (64)
    k_agg<<<aggBlocks, 256>>>((const float4*)h2, agg4, Nn);
    k_gemm_mma<64><<<gemmBlocks, 256, smem64>>>(agg4, (const float4*)h2,
        wimg + 2 * 131072, bl2, g2, be2, h1, Nn);

    // pooling + head
    int poolWarps = (Nn + 63) / 64;
    k_pool<<<(poolWarps * 32 + 255) / 256, 256>>>(h1, bat, Nn);
    k_head<<<1, 256>>>(cW1, cb1, cW2, cb2, out);
}